// round 5
// baseline (speedup 1.0000x reference)
#include <cuda_runtime.h>

// ---------------- scratch (sizes fixed for this problem) ----------------
__device__ float g_agg [50048  * 80];   // per-node gated sums: 32 silu'd scalars + 48 vec comps
__device__ float g_agg2[50048  * 40];   // after Lms/Lmv fold: 16 s + 24 v
__device__ float g_mid [400000 * 40];   // stage-1 per-edge intermediate
__device__ float g_gate[16 * 400000];   // sigmoid gates, t-major [16][E]
__device__ float g_hid [48 * 50048];    // update hidden scalars (silu'd / sigm'd), t-major
__device__ float g_hidv[48 * 50048];    // update gated vector comps, (k*3+c)-major

#define I2f   0.70710678118654752f
#define I3f   0.57735026918962576f
#define R128f 0.08838834764831845f
#define R32f  0.17677669529663687f

__device__ __forceinline__ float sigm_f(float x) {
    return __fdividef(1.f, 1.f + __expf(-x));
}

__device__ __forceinline__ void wload(float* __restrict__ dst, const float* __restrict__ src,
                                      int nf4, float sc, int tid, int nt) {
    for (int t = tid; t < nf4; t += nt) {
        float4 v = reinterpret_cast<const float4*>(src)[t];
        v.x *= sc; v.y *= sc; v.z *= sc; v.w *= sc;
        reinterpret_cast<float4*>(dst)[t] = v;
    }
}
__device__ __forceinline__ void wslice(float* __restrict__ dst, const float* __restrict__ src,
                                       int rows, int srcF4, int dstF4, int off4,
                                       float sc, int tid) {
    int n = rows * dstF4;
    for (int t = tid; t < n; t += 128) {
        int r = t / dstF4, o = t - r * dstF4;
        float4 v = reinterpret_cast<const float4*>(src)[r * srcF4 + off4 + o];
        v.x *= sc; v.y *= sc; v.z *= sc; v.w *= sc;
        reinterpret_cast<float4*>(dst)[t] = v;
    }
}

template<int K4>
__device__ __forceinline__ void fma_k(float* acc, const float* __restrict__ w, float p) {
#pragma unroll
    for (int k = 0; k < K4; k++) {
        float4 ww = reinterpret_cast<const float4*>(w)[k];
        acc[4 * k + 0] += p * ww.x; acc[4 * k + 1] += p * ww.y;
        acc[4 * k + 2] += p * ww.z; acc[4 * k + 3] += p * ww.w;
    }
}
// dual-edge: one weight load feeds both accumulators
template<int K4>
__device__ __forceinline__ void fma_k2(float* a0, float* a1, const float* __restrict__ w,
                                       float p0, float p1) {
#pragma unroll
    for (int k = 0; k < K4; k++) {
        float4 ww = reinterpret_cast<const float4*>(w)[k];
        a0[4 * k + 0] += p0 * ww.x; a0[4 * k + 1] += p0 * ww.y;
        a0[4 * k + 2] += p0 * ww.z; a0[4 * k + 3] += p0 * ww.w;
        a1[4 * k + 0] += p1 * ww.x; a1[4 * k + 1] += p1 * ww.y;
        a1[4 * k + 2] += p1 * ww.z; a1[4 * k + 3] += p1 * ww.w;
    }
}
__device__ __forceinline__ void fma_vo8(float* vo, const float* A, float bx, float by, float bz) {
#pragma unroll
    for (int k = 0; k < 8; k++) {
        vo[3 * k + 0] += A[k] * bx; vo[3 * k + 1] += A[k] * by; vo[3 * k + 2] += A[k] * bz;
    }
}
__device__ __forceinline__ void fma_cross8_2(float* v0, float* v1, const float* __restrict__ w,
    float c0x, float c0y, float c0z, float c1x, float c1y, float c1z) {
#pragma unroll
    for (int q = 0; q < 2; q++) {
        float4 ww = reinterpret_cast<const float4*>(w)[q];
        v0[12 * q + 0] += c0x * ww.x; v0[12 * q + 1]  += c0y * ww.x; v0[12 * q + 2]  += c0z * ww.x;
        v0[12 * q + 3] += c0x * ww.y; v0[12 * q + 4]  += c0y * ww.y; v0[12 * q + 5]  += c0z * ww.y;
        v0[12 * q + 6] += c0x * ww.z; v0[12 * q + 7]  += c0y * ww.z; v0[12 * q + 8]  += c0z * ww.z;
        v0[12 * q + 9] += c0x * ww.w; v0[12 * q + 10] += c0y * ww.w; v0[12 * q + 11] += c0z * ww.w;
        v1[12 * q + 0] += c1x * ww.x; v1[12 * q + 1]  += c1y * ww.x; v1[12 * q + 2]  += c1z * ww.x;
        v1[12 * q + 3] += c1x * ww.y; v1[12 * q + 4]  += c1y * ww.y; v1[12 * q + 5]  += c1z * ww.y;
        v1[12 * q + 6] += c1x * ww.z; v1[12 * q + 7]  += c1y * ww.z; v1[12 * q + 8]  += c1z * ww.z;
        v1[12 * q + 9] += c1x * ww.w; v1[12 * q + 10] += c1y * ww.w; v1[12 * q + 11] += c1z * ww.w;
    }
}
__device__ __forceinline__ void ld_f(float* dst, const float* __restrict__ src, int nf4) {
#pragma unroll
    for (int q = 0; q < 6; q++)
        if (q < nf4) reinterpret_cast<float4*>(dst)[q] =
            __ldg(reinterpret_cast<const float4*>(src) + q);
}

// ---------------- kernels ----------------
__global__ void zero_kernel(int n) {
    int i = blockIdx.x * 256 + threadIdx.x;
    if (i < n) g_agg[i] = 0.f;
}

// stage1 scalar paths (2 edges/thread): ms[16] -> g_mid[e][0:16)
__global__ __launch_bounds__(128, 3) void stage1_s_kernel(
    const float* __restrict__ ns, const float* __restrict__ nv,
    const int* __restrict__ eidx,
    const float* __restrict__ W1ss, const float* __restrict__ W1vvs, int E)
{
    __shared__ float wss[4096], wd[1024];
    int tid = threadIdx.x;
    wload(wss, W1ss, 1024, I2f / 16.f, tid, 128);
    wload(wd, W1vvs, 256, I2f * I3f / 8.f, tid, 128);
    __syncthreads();
    int e0 = blockIdx.x * 256 + tid;
    if (e0 >= E) return;
    int e1 = e0 + 128;
    bool a1 = e1 < E;
    int e1c = a1 ? e1 : e0;
    int r0 = eidx[e0], c0 = eidx[E + e0];
    int r1 = eidx[e1c], c1 = eidx[E + e1c];

    float acc0[16], acc1[16];
#pragma unroll
    for (int k = 0; k < 16; k++) { acc0[k] = 0.f; acc1[k] = 0.f; }
    {
        float s1a[16], s2a[16], s1b[16], s2b[16];
        ld_f(s1a, ns + (size_t)r0 * 16, 4); ld_f(s2a, ns + (size_t)c0 * 16, 4);
        ld_f(s1b, ns + (size_t)r1 * 16, 4); ld_f(s2b, ns + (size_t)c1 * 16, 4);
#pragma unroll 1
        for (int i = 0; i < 16; i++) {
            float x0 = s1a[i], x1 = s1b[i];
#pragma unroll 2
            for (int j = 0; j < 16; j++)
                fma_k2<4>(acc0, acc1, &wss[(i * 16 + j) * 16], x0 * s2a[j], x1 * s2b[j]);
        }
    }
    {
        float v1a[24], v2a[24], v1b[24], v2b[24];
        ld_f(v1a, nv + (size_t)r0 * 24, 6); ld_f(v2a, nv + (size_t)c0 * 24, 6);
        ld_f(v1b, nv + (size_t)r1 * 24, 6); ld_f(v2b, nv + (size_t)c1 * 24, 6);
#pragma unroll 1
        for (int i = 0; i < 8; i++) {
            float ax0 = v1a[3 * i], ay0 = v1a[3 * i + 1], az0 = v1a[3 * i + 2];
            float ax1 = v1b[3 * i], ay1 = v1b[3 * i + 1], az1 = v1b[3 * i + 2];
#pragma unroll 2
            for (int j = 0; j < 8; j++) {
                float d0 = ax0 * v2a[3 * j] + ay0 * v2a[3 * j + 1] + az0 * v2a[3 * j + 2];
                float d1 = ax1 * v2b[3 * j] + ay1 * v2b[3 * j + 1] + az1 * v2b[3 * j + 2];
                fma_k2<4>(acc0, acc1, &wd[(i * 8 + j) * 16], d0, d1);
            }
        }
    }
    float* o0 = &g_mid[(size_t)e0 * 40];
#pragma unroll
    for (int q = 0; q < 4; q++)
        reinterpret_cast<float4*>(o0)[q] = reinterpret_cast<float4*>(acc0)[q];
    if (a1) {
        float* o1 = &g_mid[(size_t)e1 * 40];
#pragma unroll
        for (int q = 0; q < 4; q++)
            reinterpret_cast<float4*>(o1)[q] = reinterpret_cast<float4*>(acc1)[q];
    }
}

// stage1 vector paths (2 edges/thread): mv[8][3] -> g_mid[e][16:40)
__global__ __launch_bounds__(128, 3) void stage1_v_kernel(
    const float* __restrict__ ns, const float* __restrict__ nv,
    const int* __restrict__ eidx,
    const float* __restrict__ W1sv, const float* __restrict__ W1vs,
    const float* __restrict__ W1vvv, int E)
{
    __shared__ float wsv[1024], wvs[1024], wvvv[512];
    int tid = threadIdx.x;
    wload(wsv, W1sv, 256, I3f * R128f, tid, 128);
    wload(wvs, W1vs, 256, I3f * R128f, tid, 128);
    wload(wvvv, W1vvv, 128, I2f * I3f / 8.f, tid, 128);
    __syncthreads();
    int e0 = blockIdx.x * 256 + tid;
    if (e0 >= E) return;
    int e1 = e0 + 128;
    bool a1 = e1 < E;
    int e1c = a1 ? e1 : e0;
    int r0 = eidx[e0], c0 = eidx[E + e0];
    int r1 = eidx[e1c], c1 = eidx[E + e1c];

    float vo0[24], vo1[24];
#pragma unroll
    for (int k = 0; k < 24; k++) { vo0[k] = 0.f; vo1[k] = 0.f; }
    {   // 0x1 -> 1
        float s1a[16], s1b[16], v2a[24], v2b[24];
        ld_f(s1a, ns + (size_t)r0 * 16, 4); ld_f(s1b, ns + (size_t)r1 * 16, 4);
        ld_f(v2a, nv + (size_t)c0 * 24, 6); ld_f(v2b, nv + (size_t)c1 * 24, 6);
#pragma unroll 1
        for (int j = 0; j < 8; j++) {
            float A0[8], A1[8];
#pragma unroll
            for (int k = 0; k < 8; k++) { A0[k] = 0.f; A1[k] = 0.f; }
#pragma unroll 2
            for (int i = 0; i < 16; i++)
                fma_k2<2>(A0, A1, &wsv[(i * 8 + j) * 8], s1a[i], s1b[i]);
            fma_vo8(vo0, A0, v2a[3 * j], v2a[3 * j + 1], v2a[3 * j + 2]);
            fma_vo8(vo1, A1, v2b[3 * j], v2b[3 * j + 1], v2b[3 * j + 2]);
        }
    }
    {   // 1x0 -> 1
        float s2a[16], s2b[16], v1a[24], v1b[24];
        ld_f(s2a, ns + (size_t)c0 * 16, 4); ld_f(s2b, ns + (size_t)c1 * 16, 4);
        ld_f(v1a, nv + (size_t)r0 * 24, 6); ld_f(v1b, nv + (size_t)r1 * 24, 6);
#pragma unroll 1
        for (int i = 0; i < 8; i++) {
            float A0[8], A1[8];
#pragma unroll
            for (int k = 0; k < 8; k++) { A0[k] = 0.f; A1[k] = 0.f; }
#pragma unroll 2
            for (int j = 0; j < 16; j++)
                fma_k2<2>(A0, A1, &wvs[(i * 16 + j) * 8], s2a[j], s2b[j]);
            fma_vo8(vo0, A0, v1a[3 * i], v1a[3 * i + 1], v1a[3 * i + 2]);
            fma_vo8(vo1, A1, v1b[3 * i], v1b[3 * i + 1], v1b[3 * i + 2]);
        }
    }
    {   // 1x1 -> 1
        float v1a[24], v1b[24], v2a[24], v2b[24];
        ld_f(v1a, nv + (size_t)r0 * 24, 6); ld_f(v1b, nv + (size_t)r1 * 24, 6);
        ld_f(v2a, nv + (size_t)c0 * 24, 6); ld_f(v2b, nv + (size_t)c1 * 24, 6);
#pragma unroll 1
        for (int i = 0; i < 8; i++) {
            float ax0 = v1a[3 * i], ay0 = v1a[3 * i + 1], az0 = v1a[3 * i + 2];
            float ax1 = v1b[3 * i], ay1 = v1b[3 * i + 1], az1 = v1b[3 * i + 2];
#pragma unroll 1
            for (int j = 0; j < 8; j++) {
                float bx0 = v2a[3 * j], by0 = v2a[3 * j + 1], bz0 = v2a[3 * j + 2];
                float bx1 = v2b[3 * j], by1 = v2b[3 * j + 1], bz1 = v2b[3 * j + 2];
                fma_cross8_2(vo0, vo1, &wvvv[(i * 8 + j) * 8],
                             ay0 * bz0 - az0 * by0, az0 * bx0 - ax0 * bz0, ax0 * by0 - ay0 * bx0,
                             ay1 * bz1 - az1 * by1, az1 * bx1 - ax1 * bz1, ax1 * by1 - ay1 * bx1);
            }
        }
    }
    float* o0 = &g_mid[(size_t)e0 * 40 + 16];
#pragma unroll
    for (int q = 0; q < 6; q++)
        reinterpret_cast<float4*>(o0)[q] = reinterpret_cast<float4*>(vo0)[q];
    if (a1) {
        float* o1 = &g_mid[(size_t)e1 * 40 + 16];
#pragma unroll
        for (int q = 0; q < 6; q++)
            reinterpret_cast<float4*>(o1)[q] = reinterpret_cast<float4*>(vo1)[q];
    }
}

// stage2 scalar paths (2 edges/thread), 3 k-chunks of 16
__global__ __launch_bounds__(128, 3) void stage2_s_kernel(
    const float* __restrict__ edge_s, const float* __restrict__ edge_v,
    const int* __restrict__ eidx,
    const float* __restrict__ W2ss, const float* __restrict__ W2vvs, int E)
{
    __shared__ float ws[2048], wd[1024];
    int tid = threadIdx.x;
    int e0 = blockIdx.x * 256 + tid;
    bool act = e0 < E;
    int e1 = e0 + 128;
    bool a1 = e1 < E;
    int e0c = act ? e0 : 0;
    int e1c = a1 ? e1 : e0c;
    int c0 = eidx[E + e0c], c1 = eidx[E + e1c];
#pragma unroll 1
    for (int ch = 0; ch < 3; ch++) {
        __syncthreads();
        wslice(ws, W2ss, 128, 12, 4, ch * 4, I2f * R128f, tid);
        wslice(wd, W2vvs, 64, 12, 4, ch * 4, I2f * I3f / 8.f, tid);
        __syncthreads();
        if (!act) continue;
        float acc0[16], acc1[16];
#pragma unroll
        for (int k = 0; k < 16; k++) { acc0[k] = 0.f; acc1[k] = 0.f; }
        {
            float msa[16], msb[16], esa[8], esb[8];
            ld_f(msa, &g_mid[(size_t)e0c * 40], 4);
            ld_f(msb, &g_mid[(size_t)e1c * 40], 4);
            ld_f(esa, edge_s + (size_t)e0c * 8, 2);
            ld_f(esb, edge_s + (size_t)e1c * 8, 2);
#pragma unroll 1
            for (int i = 0; i < 16; i++) {
                float x0 = msa[i], x1 = msb[i];
#pragma unroll 2
                for (int j = 0; j < 8; j++)
                    fma_k2<4>(acc0, acc1, &ws[(i * 8 + j) * 16], x0 * esa[j], x1 * esb[j]);
            }
        }
        {
            float mva[24], mvb[24], eva[24], evb[24];
            ld_f(mva, &g_mid[(size_t)e0c * 40 + 16], 6);
            ld_f(mvb, &g_mid[(size_t)e1c * 40 + 16], 6);
            ld_f(eva, edge_v + (size_t)e0c * 24, 6);
            ld_f(evb, edge_v + (size_t)e1c * 24, 6);
#pragma unroll 1
            for (int i = 0; i < 8; i++) {
                float ax0 = mva[3 * i], ay0 = mva[3 * i + 1], az0 = mva[3 * i + 2];
                float ax1 = mvb[3 * i], ay1 = mvb[3 * i + 1], az1 = mvb[3 * i + 2];
#pragma unroll 2
                for (int j = 0; j < 8; j++) {
                    float d0 = ax0 * eva[3 * j] + ay0 * eva[3 * j + 1] + az0 * eva[3 * j + 2];
                    float d1 = ax1 * evb[3 * j] + ay1 * evb[3 * j + 1] + az1 * evb[3 * j + 2];
                    fma_k2<4>(acc0, acc1, &wd[(i * 8 + j) * 16], d0, d1);
                }
            }
        }
        if (ch < 2) {
            float* d0 = &g_agg[(size_t)c0 * 80 + ch * 16];
#pragma unroll
            for (int t = 0; t < 16; t++)
                atomicAdd(d0 + t, acc0[t] * sigm_f(acc0[t]));
            if (a1) {
                float* d1 = &g_agg[(size_t)c1 * 80 + ch * 16];
#pragma unroll
                for (int t = 0; t < 16; t++)
                    atomicAdd(d1 + t, acc1[t] * sigm_f(acc1[t]));
            }
        } else {
#pragma unroll
            for (int t = 0; t < 16; t++)
                g_gate[(size_t)t * E + e0] = sigm_f(acc0[t]);
            if (a1) {
#pragma unroll
                for (int t = 0; t < 16; t++)
                    g_gate[(size_t)t * E + e1] = sigm_f(acc1[t]);
            }
        }
    }
}

// stage2 vector paths (2 edges/thread), 2 k-chunks of 8
__global__ __launch_bounds__(128, 3) void stage2_v_kernel(
    const float* __restrict__ edge_s, const float* __restrict__ edge_v,
    const int* __restrict__ eidx,
    const float* __restrict__ W2sv, const float* __restrict__ W2vs,
    const float* __restrict__ W2vvv, int E)
{
    __shared__ float wsv[1024], wvs[1024], wvvv[512];
    int tid = threadIdx.x;
    int e0 = blockIdx.x * 256 + tid;
    bool act = e0 < E;
    int e1 = e0 + 128;
    bool a1 = e1 < E;
    int e0c = act ? e0 : 0;
    int e1c = a1 ? e1 : e0c;
    int c0 = eidx[E + e0c], c1 = eidx[E + e1c];
#pragma unroll 1
    for (int ch = 0; ch < 2; ch++) {
        __syncthreads();
        wslice(wsv, W2sv, 128, 4, 2, ch * 2, I3f * R128f, tid);
        wslice(wvs, W2vs, 64, 4, 2, ch * 2, I3f / 8.f, tid);
        wslice(wvvv, W2vvv, 64, 4, 2, ch * 2, I2f * I3f / 8.f, tid);
        __syncthreads();
        if (!act) continue;
        float vo0[24], vo1[24];
#pragma unroll
        for (int k = 0; k < 24; k++) { vo0[k] = 0.f; vo1[k] = 0.f; }
        {   // 0x1
            float msa[16], msb[16], eva[24], evb[24];
            ld_f(msa, &g_mid[(size_t)e0c * 40], 4);
            ld_f(msb, &g_mid[(size_t)e1c * 40], 4);
            ld_f(eva, edge_v + (size_t)e0c * 24, 6);
            ld_f(evb, edge_v + (size_t)e1c * 24, 6);
#pragma unroll 1
            for (int j = 0; j < 8; j++) {
                float A0[8], A1[8];
#pragma unroll
                for (int k = 0; k < 8; k++) { A0[k] = 0.f; A1[k] = 0.f; }
#pragma unroll 2
                for (int i = 0; i < 16; i++)
                    fma_k2<2>(A0, A1, &wsv[(i * 8 + j) * 8], msa[i], msb[i]);
                fma_vo8(vo0, A0, eva[3 * j], eva[3 * j + 1], eva[3 * j + 2]);
                fma_vo8(vo1, A1, evb[3 * j], evb[3 * j + 1], evb[3 * j + 2]);
            }
        }
        {   // 1x0
            float esa[8], esb[8], mva[24], mvb[24];
            ld_f(esa, edge_s + (size_t)e0c * 8, 2);
            ld_f(esb, edge_s + (size_t)e1c * 8, 2);
            ld_f(mva, &g_mid[(size_t)e0c * 40 + 16], 6);
            ld_f(mvb, &g_mid[(size_t)e1c * 40 + 16], 6);
#pragma unroll 1
            for (int i = 0; i < 8; i++) {
                float A0[8], A1[8];
#pragma unroll
                for (int k = 0; k < 8; k++) { A0[k] = 0.f; A1[k] = 0.f; }
#pragma unroll 2
                for (int j = 0; j < 8; j++)
                    fma_k2<2>(A0, A1, &wvs[(i * 8 + j) * 8], esa[j], esb[j]);
                fma_vo8(vo0, A0, mva[3 * i], mva[3 * i + 1], mva[3 * i + 2]);
                fma_vo8(vo1, A1, mvb[3 * i], mvb[3 * i + 1], mvb[3 * i + 2]);
            }
        }
        {   // 1x1 cross
            float mva[24], mvb[24], eva[24], evb[24];
            ld_f(mva, &g_mid[(size_t)e0c * 40 + 16], 6);
            ld_f(mvb, &g_mid[(size_t)e1c * 40 + 16], 6);
            ld_f(eva, edge_v + (size_t)e0c * 24, 6);
            ld_f(evb, edge_v + (size_t)e1c * 24, 6);
#pragma unroll 1
            for (int i = 0; i < 8; i++) {
                float ax0 = mva[3 * i], ay0 = mva[3 * i + 1], az0 = mva[3 * i + 2];
                float ax1 = mvb[3 * i], ay1 = mvb[3 * i + 1], az1 = mvb[3 * i + 2];
#pragma unroll 1
                for (int j = 0; j < 8; j++) {
                    float bx0 = eva[3 * j], by0 = eva[3 * j + 1], bz0 = eva[3 * j + 2];
                    float bx1 = evb[3 * j], by1 = evb[3 * j + 1], bz1 = evb[3 * j + 2];
                    fma_cross8_2(vo0, vo1, &wvvv[(i * 8 + j) * 8],
                                 ay0 * bz0 - az0 * by0, az0 * bx0 - ax0 * bz0, ax0 * by0 - ay0 * bx0,
                                 ay1 * bz1 - az1 * by1, az1 * bx1 - ax1 * bz1, ax1 * by1 - ay1 * bx1);
                }
            }
        }
#pragma unroll
        for (int t = 0; t < 8; t++) {
            float g0 = g_gate[(size_t)(ch * 8 + t) * E + e0];
            float* d0 = &g_agg[(size_t)c0 * 80 + 32 + (ch * 8 + t) * 3];
            atomicAdd(d0 + 0, vo0[3 * t + 0] * g0);
            atomicAdd(d0 + 1, vo0[3 * t + 1] * g0);
            atomicAdd(d0 + 2, vo0[3 * t + 2] * g0);
        }
        if (a1) {
#pragma unroll
            for (int t = 0; t < 8; t++) {
                float g1 = g_gate[(size_t)(ch * 8 + t) * E + e1];
                float* d1 = &g_agg[(size_t)c1 * 80 + 32 + (ch * 8 + t) * 3];
                atomicAdd(d1 + 0, vo1[3 * t + 0] * g1);
                atomicAdd(d1 + 1, vo1[3 * t + 1] * g1);
                atomicAdd(d1 + 2, vo1[3 * t + 2] * g1);
            }
        }
    }
}

// fold Lms/Lmv into aggregated (post-gate) sums: g_agg[N,80] -> g_agg2[N,40]
__global__ void fold_kernel(const float* __restrict__ Lms, const float* __restrict__ Lmv, int N)
{
    __shared__ float lms[512], lmv[128];
    int tid = threadIdx.x;
    wload(lms, Lms, 128, R32f, tid, 256);
    wload(lmv, Lmv, 32, 0.25f, tid, 256);
    __syncthreads();
    int n = blockIdx.x * 256 + tid;
    if (n >= N) return;
    const float* a = &g_agg[(size_t)n * 80];
    float* o = &g_agg2[(size_t)n * 40];
    float os[16];
#pragma unroll
    for (int k = 0; k < 16; k++) os[k] = 0.f;
#pragma unroll 1
    for (int i = 0; i < 32; i++)
        fma_k<4>(os, &lms[i * 16], a[i]);
#pragma unroll
    for (int k = 0; k < 16; k++) o[k] = os[k];
    float ov[24];
#pragma unroll
    for (int k = 0; k < 24; k++) ov[k] = 0.f;
#pragma unroll 1
    for (int i = 0; i < 16; i++) {
        float ax = a[32 + 3 * i], ay = a[32 + 3 * i + 1], az = a[32 + 3 * i + 2];
        const float* w = &lmv[i * 8];
#pragma unroll
        for (int k = 0; k < 8; k++) {
            float ww = w[k];
            ov[3 * k + 0] += ax * ww; ov[3 * k + 1] += ay * ww; ov[3 * k + 2] += az * ww;
        }
    }
#pragma unroll
    for (int t = 0; t < 24; t++) o[16 + t] = ov[t];
}

// update scalar paths -> g_hid (silu'd for k<32, sigm'd for k>=32)
__global__ __launch_bounds__(128, 5) void update_s_kernel(
    const float* __restrict__ ns, const float* __restrict__ nv,
    const float* __restrict__ W3ss, const float* __restrict__ W3vvs, int N)
{
    __shared__ float ws[4096], wd[1024];
    int tid = threadIdx.x;
    int n = blockIdx.x * 128 + tid;
    bool act = n < N;
    float s1[16], v1[24], s2[16], v2[24];
    if (act) {
        ld_f(s1, ns + (size_t)n * 16, 4);
        ld_f(v1, nv + (size_t)n * 24, 6);
        const float* a = &g_agg2[(size_t)n * 40];
#pragma unroll
        for (int q = 0; q < 4; q++) reinterpret_cast<float4*>(s2)[q] = reinterpret_cast<const float4*>(a)[q];
#pragma unroll
        for (int q = 0; q < 6; q++) reinterpret_cast<float4*>(v2)[q] = reinterpret_cast<const float4*>(a)[4 + q];
    }
#pragma unroll 1
    for (int ch = 0; ch < 3; ch++) {
        __syncthreads();
        wslice(ws, W3ss, 256, 12, 4, ch * 4, I2f / 16.f, tid);
        wslice(wd, W3vvs, 64, 12, 4, ch * 4, I2f * I3f / 8.f, tid);
        __syncthreads();
        if (!act) continue;
        float acc[16];
#pragma unroll
        for (int k = 0; k < 16; k++) acc[k] = 0.f;
#pragma unroll 1
        for (int i = 0; i < 16; i++) {
            float a = s1[i];
#pragma unroll 2
            for (int j = 0; j < 16; j++)
                fma_k<4>(acc, &ws[(i * 16 + j) * 16], a * s2[j]);
        }
#pragma unroll 1
        for (int i = 0; i < 8; i++) {
            float ax = v1[3 * i], ay = v1[3 * i + 1], az = v1[3 * i + 2];
#pragma unroll 2
            for (int j = 0; j < 8; j++) {
                float d = ax * v2[3 * j] + ay * v2[3 * j + 1] + az * v2[3 * j + 2];
                fma_k<4>(acc, &wd[(i * 8 + j) * 16], d);
            }
        }
#pragma unroll
        for (int t = 0; t < 16; t++) {
            float v = (ch < 2) ? acc[t] * sigm_f(acc[t]) : sigm_f(acc[t]);
            g_hid[(size_t)(ch * 16 + t) * N + n] = v;
        }
    }
}

// update vector paths -> gated comps in g_hidv
__global__ __launch_bounds__(128, 5) void update_v_kernel(
    const float* __restrict__ ns, const float* __restrict__ nv,
    const float* __restrict__ W3sv, const float* __restrict__ W3vs,
    const float* __restrict__ W3vvv, int N)
{
    __shared__ float wsv[1024], wvs[1024], wvvv[512];
    int tid = threadIdx.x;
    int n = blockIdx.x * 128 + tid;
    bool act = n < N;
    float s1[16], v1[24], s2[16], v2[24];
    if (act) {
        ld_f(s1, ns + (size_t)n * 16, 4);
        ld_f(v1, nv + (size_t)n * 24, 6);
        const float* a = &g_agg2[(size_t)n * 40];
#pragma unroll
        for (int q = 0; q < 4; q++) reinterpret_cast<float4*>(s2)[q] = reinterpret_cast<const float4*>(a)[q];
#pragma unroll
        for (int q = 0; q < 6; q++) reinterpret_cast<float4*>(v2)[q] = reinterpret_cast<const float4*>(a)[4 + q];
    }
#pragma unroll 1
    for (int ch = 0; ch < 2; ch++) {
        __syncthreads();
        wslice(wsv, W3sv, 128, 4, 2, ch * 2, I3f * R128f, tid);
        wslice(wvs, W3vs, 128, 4, 2, ch * 2, I3f * R128f, tid);
        wslice(wvvv, W3vvv, 64, 4, 2, ch * 2, I2f * I3f / 8.f, tid);
        __syncthreads();
        if (!act) continue;
        float vo[24];
#pragma unroll
        for (int k = 0; k < 24; k++) vo[k] = 0.f;
#pragma unroll 1
        for (int j = 0; j < 8; j++) {
            float A[8];
#pragma unroll
            for (int k = 0; k < 8; k++) A[k] = 0.f;
#pragma unroll 2
            for (int i = 0; i < 16; i++)
                fma_k<2>(A, &wsv[(i * 8 + j) * 8], s1[i]);
            fma_vo8(vo, A, v2[3 * j], v2[3 * j + 1], v2[3 * j + 2]);
        }
#pragma unroll 1
        for (int i = 0; i < 8; i++) {
            float A[8];
#pragma unroll
            for (int k = 0; k < 8; k++) A[k] = 0.f;
#pragma unroll 2
            for (int j = 0; j < 16; j++)
                fma_k<2>(A, &wvs[(i * 16 + j) * 8], s2[j]);
            fma_vo8(vo, A, v1[3 * i], v1[3 * i + 1], v1[3 * i + 2]);
        }
#pragma unroll 1
        for (int i = 0; i < 8; i++) {
            float ax = v1[3 * i], ay = v1[3 * i + 1], az = v1[3 * i + 2];
#pragma unroll 1
            for (int j = 0; j < 8; j++) {
                float bx = v2[3 * j], by = v2[3 * j + 1], bz = v2[3 * j + 2];
                float cx = ay * bz - az * by, cy = az * bx - ax * bz, cz = ax * by - ay * bx;
                const float* w = &wvvv[(i * 8 + j) * 8];
#pragma unroll
                for (int q = 0; q < 2; q++) {
                    float4 ww = reinterpret_cast<const float4*>(w)[q];
                    vo[12 * q + 0] += cx * ww.x; vo[12 * q + 1]  += cy * ww.x; vo[12 * q + 2]  += cz * ww.x;
                    vo[12 * q + 3] += cx * ww.y; vo[12 * q + 4]  += cy * ww.y; vo[12 * q + 5]  += cz * ww.y;
                    vo[12 * q + 6] += cx * ww.z; vo[12 * q + 7]  += cy * ww.z; vo[12 * q + 8]  += cz * ww.z;
                    vo[12 * q + 9] += cx * ww.w; vo[12 * q + 10] += cy * ww.w; vo[12 * q + 11] += cz * ww.w;
                }
            }
        }
#pragma unroll
        for (int t = 0; t < 8; t++) {
            float g = g_hid[(size_t)(32 + ch * 8 + t) * N + n];
#pragma unroll
            for (int cc = 0; cc < 3; cc++)
                g_hidv[(size_t)((ch * 8 + t) * 3 + cc) * N + n] = vo[3 * t + cc] * g;
        }
    }
}

// final: apply Lus/Luv per node, write out[N,40]
__global__ void final_kernel(const float* __restrict__ Lus, const float* __restrict__ Luv,
                             float* __restrict__ out, int N)
{
    __shared__ float lus[512], luv[128];
    int tid = threadIdx.x;
    wload(lus, Lus, 128, R32f, tid, 256);
    wload(luv, Luv, 32, 0.25f, tid, 256);
    __syncthreads();
    int n = blockIdx.x * 256 + tid;
    if (n >= N) return;
    float os[16];
#pragma unroll
    for (int k = 0; k < 16; k++) os[k] = 0.f;
#pragma unroll 1
    for (int i = 0; i < 32; i++)
        fma_k<4>(os, &lus[i * 16], g_hid[(size_t)i * N + n]);
    float ov[24];
#pragma unroll
    for (int k = 0; k < 24; k++) ov[k] = 0.f;
#pragma unroll 1
    for (int i = 0; i < 16; i++) {
        float ax = g_hidv[(size_t)(3 * i + 0) * N + n];
        float ay = g_hidv[(size_t)(3 * i + 1) * N + n];
        float az = g_hidv[(size_t)(3 * i + 2) * N + n];
        const float* w = &luv[i * 8];
#pragma unroll
        for (int k = 0; k < 8; k++) {
            float ww = w[k];
            ov[3 * k + 0] += ax * ww; ov[3 * k + 1] += ay * ww; ov[3 * k + 2] += az * ww;
        }
    }
    float* o = out + (size_t)n * 40;
#pragma unroll
    for (int k = 0; k < 16; k++) o[k] = os[k];
#pragma unroll
    for (int t = 0; t < 24; t++) o[16 + t] = ov[t];
}

// ---------------- launch ----------------
extern "C" void kernel_launch(void* const* d_in, const int* in_sizes, int n_in,
                              void* d_out, int out_size) {
    const float* node_s = (const float*)d_in[0];
    const float* node_v = (const float*)d_in[1];
    const float* edge_s = (const float*)d_in[3];
    const float* edge_v = (const float*)d_in[4];
    const int*   eidx   = (const int*)d_in[5];
    const float* W1ss = (const float*)d_in[6];
    const float* W1sv = (const float*)d_in[7];
    const float* W1vs = (const float*)d_in[8];
    const float* W1vvs = (const float*)d_in[9];
    const float* W1vvv = (const float*)d_in[10];
    const float* W2ss = (const float*)d_in[11];
    const float* W2sv = (const float*)d_in[12];
    const float* W2vs = (const float*)d_in[13];
    const float* W2vvs = (const float*)d_in[14];
    const float* W2vvv = (const float*)d_in[15];
    const float* Lms = (const float*)d_in[16];
    const float* Lmv = (const float*)d_in[17];
    const float* W3ss = (const float*)d_in[18];
    const float* W3sv = (const float*)d_in[19];
    const float* W3vs = (const float*)d_in[20];
    const float* W3vvs = (const float*)d_in[21];
    const float* W3vvv = (const float*)d_in[22];
    const float* Lus = (const float*)d_in[23];
    const float* Luv = (const float*)d_in[24];
    float* out = (float*)d_out;

    int N = in_sizes[0] / 16;
    int E = in_sizes[3] / 8;
    int gE2 = (E + 255) / 256;   // 2 edges per thread
    int gN = (N + 127) / 128;

    zero_kernel<<<(N * 80 + 255) / 256, 256>>>(N * 80);
    stage1_s_kernel<<<gE2, 128>>>(node_s, node_v, eidx, W1ss, W1vvs, E);
    stage1_v_kernel<<<gE2, 128>>>(node_s, node_v, eidx, W1sv, W1vs, W1vvv, E);
    stage2_s_kernel<<<gE2, 128>>>(edge_s, edge_v, eidx, W2ss, W2vvs, E);
    stage2_v_kernel<<<gE2, 128>>>(edge_s, edge_v, eidx, W2sv, W2vs, W2vvv, E);
    fold_kernel<<<(N + 255) / 256, 256>>>(Lms, Lmv, N);
    update_s_kernel<<<gN, 128>>>(node_s, node_v, W3ss, W3vvs, N);
    update_v_kernel<<<gN, 128>>>(node_s, node_v, W3sv, W3vs, W3vvv, N);
    final_kernel<<<(N + 255) / 256, 256>>>(Lus, Luv, out, N);
}